// round 6
// baseline (speedup 1.0000x reference)
#include <cuda_runtime.h>
#include <cstdint>

#define Tn 2048
#define Bn 256
#define Hn 128

// Layer-0 hidden states, layout [T][128 j][256 b] (batch-major innermost)
__device__ float g_h1[(size_t)Tn * Hn * Bn];

__device__ __forceinline__ uint32_t smem_u32(const void* p) {
    return (uint32_t)__cvta_generic_to_shared(p);
}
__device__ __forceinline__ void cluster_arrive_() {
    asm volatile("barrier.cluster.arrive.aligned;" ::: "memory");
}
__device__ __forceinline__ void cluster_wait_() {
    asm volatile("barrier.cluster.wait.aligned;" ::: "memory");
}
__device__ __forceinline__ uint32_t mapa_sh(uint32_t addr, uint32_t rank) {
    uint32_t r;
    asm("mapa.shared::cluster.u32 %0, %1, %2;" : "=r"(r) : "r"(addr), "r"(rank));
    return r;
}
__device__ __forceinline__ void st_dsmem(uint32_t addr, float v) {
    asm volatile("st.shared::cluster.f32 [%0], %1;" :: "r"(addr), "f"(v) : "memory");
}
__device__ __forceinline__ float sigm(float v) { return 1.0f / (1.0f + __expf(-v)); }
__device__ __forceinline__ float tanh_(float v) { return 2.0f / (1.0f + __expf(-2.0f * v)) - 1.0f; }

// packed f32x2 helpers (SASS FFMA2 — only reachable via PTX fma.rn.f32x2)
__device__ __forceinline__ unsigned long long pk2(float v) {
    unsigned long long r;
    asm("mov.b64 %0, {%1, %1};" : "=l"(r) : "f"(v));
    return r;
}
__device__ __forceinline__ void ffma2(unsigned long long& d, unsigned long long a,
                                      unsigned long long b) {
    asm("fma.rn.f32x2 %0, %1, %2, %0;" : "+l"(d) : "l"(a), "l"(b));
}
__device__ __forceinline__ void unpk(unsigned long long v, float& lo, float& hi) {
    asm("mov.b64 {%0, %1}, %2;" : "=f"(lo), "=f"(hi) : "l"(v));
}

// ---------------------------------------------------------------------------
// Layer 0: cluster of 2 CTAs x 512 threads. Thread = (gate-row 0..255, K-half).
// K-half 0 = OWN rank's hidden slice (ready via __syncthreads, computed BEFORE
// cluster_wait); K-half 1 = peer slice (after cluster_wait). Weights in
// registers. 4 batches/cluster, f32x2 packed math.
// Self h written with plain STS; only the peer copy goes over DSMEM, and the
// peer store is skipped on the last step (exit safety: no remote store may
// target a CTA that could have exited).
// smem (floats): hbuf [2][128][4] @0 (1024), xbuf [2][5][4] @1024 (40),
//                gbuf [2][2][256][5] @1088 (5120) -> 6208 f = 24832 B
// ---------------------------------------------------------------------------
#define SMEM0_BYTES (6208 * 4)

__global__ void __cluster_dims__(2, 1, 1) __launch_bounds__(512, 1)
lstm_layer0(const float* __restrict__ x, const float* __restrict__ Wih,
            const float* __restrict__ Whh, const float* __restrict__ bih,
            const float* __restrict__ bhh)
{
    extern __shared__ float sm[];
    float* hbuf = sm;          // [2 par][128 j][4 b]
    float* xbuf = sm + 1024;   // [2 par][5 d][4 b]
    float* gbuf = sm + 1088;   // [2 par][2 half][256 row][5]

    const int tid  = threadIdx.x;
    const int rank = blockIdx.x & 1;
    const int b0   = (blockIdx.x >> 1) * 4;

    const int row    = tid & 255;
    const int half   = tid >> 8;
    const int kslice = rank ^ half;           // 0/1: which 64-wide hidden slice
    const int grow   = ((row >> 6) << 7) + (rank << 6) + (row & 63);

    float4 w4[16];
    {
        const float4* wsrc = (const float4*)(Whh + grow * 128 + kslice * 64);
        #pragma unroll
        for (int kk = 0; kk < 16; ++kk) w4[kk] = wsrc[kk];
    }
    unsigned long long wx2[5], bb2;
    {
        float bb = bih[grow] + bhh[grow];
        bb2 = (half == 0) ? pk2(bb) : 0ull;
        #pragma unroll
        for (int d = 0; d < 5; ++d) wx2[d] = pk2(Wih[grow * 5 + d]);
    }

    for (int i = tid; i < 1024; i += 512) hbuf[i] = 0.f;
    if (tid < 20) {
        int b = tid / 5, d = tid % 5;
        xbuf[d * 4 + b] = x[((size_t)(b0 + b) * Tn) * 5 + d];
    }

    const int cb = tid >> 6, cj = tid & 63;   // combine map (tid<256)
    const int selfoff = ((rank << 6) + cj) * 4 + cb;
    uint32_t wr_peer[2];
    #pragma unroll
    for (int nbv = 0; nbv < 2; ++nbv)
        wr_peer[nbv] = mapa_sh(smem_u32(hbuf + nbv * 512 + selfoff), rank ^ 1);
    float c = 0.f;
    __syncthreads();
    cluster_arrive_();

    for (int t = 0; t < Tn; ++t) {
        const int par = t & 1, nb = par ^ 1;
        float pre = 0.f;
        if (tid < 20 && t + 1 < Tn) {
            int b = tid / 5, d = tid % 5;
            pre = x[((size_t)(b0 + b) * Tn + (t + 1)) * 5 + d];
        }
        unsigned long long a01 = bb2, a23 = bb2;
        if (half == 0) {
            const float* xb = xbuf + par * 20;
            #pragma unroll
            for (int d = 0; d < 5; ++d) {
                ffma2(a01, wx2[d], *(const unsigned long long*)(xb + d * 4));
                ffma2(a23, wx2[d], *(const unsigned long long*)(xb + d * 4 + 2));
            }
        }
        const float* hp = hbuf + par * 512 + kslice * 256;
        if (half == 0) {   // own-rank slice: ready since bar2 of previous step
            #pragma unroll
            for (int kk = 0; kk < 16; ++kk) {
                float4 wv = w4[kk];
                #pragma unroll
                for (int s = 0; s < 4; ++s) {
                    float w = (s == 0) ? wv.x : (s == 1) ? wv.y : (s == 2) ? wv.z : wv.w;
                    unsigned long long w2 = pk2(w);
                    ulonglong2 hv = *(const ulonglong2*)(hp + (kk * 4 + s) * 4);
                    ffma2(a01, w2, hv.x);
                    ffma2(a23, w2, hv.y);
                }
            }
        }
        cluster_wait_();
        if (half == 1) {   // peer slice: needs the cluster exchange
            #pragma unroll
            for (int kk = 0; kk < 16; ++kk) {
                float4 wv = w4[kk];
                #pragma unroll
                for (int s = 0; s < 4; ++s) {
                    float w = (s == 0) ? wv.x : (s == 1) ? wv.y : (s == 2) ? wv.z : wv.w;
                    unsigned long long w2 = pk2(w);
                    ulonglong2 hv = *(const ulonglong2*)(hp + (kk * 4 + s) * 4);
                    ffma2(a01, w2, hv.x);
                    ffma2(a23, w2, hv.y);
                }
            }
        }
        {   // gate partials, pitch 5 (conflict-free)
            float* gp = gbuf + ((par * 2 + half) * 256 + row) * 5;
            float g0, g1, g2, g3;
            unpk(a01, g0, g1); unpk(a23, g2, g3);
            gp[0] = g0; gp[1] = g1; gp[2] = g2; gp[3] = g3;
        }
        if (tid < 20 && t + 1 < Tn) {
            int b = tid / 5, d = tid % 5;
            xbuf[nb * 20 + d * 4 + b] = pre;
        }
        __syncthreads();                       // bar1: gbuf ready
        if (tid < 256) {
            const float* g0p = gbuf + par * 2560;        // half 0
            const float* g1p = g0p + 1280;               // half 1
            float gi = g0p[cj * 5 + cb]         + g1p[cj * 5 + cb];
            float gf = g0p[(64 + cj) * 5 + cb]  + g1p[(64 + cj) * 5 + cb];
            float gg = g0p[(128 + cj) * 5 + cb] + g1p[(128 + cj) * 5 + cb];
            float go = g0p[(192 + cj) * 5 + cb] + g1p[(192 + cj) * 5 + cb];
            float ii = sigm(gi), ff = sigm(gf), g = tanh_(gg), oo = sigm(go);
            c = fmaf(ff, c, ii * g);
            float h = oo * tanh_(c);
            hbuf[nb * 512 + selfoff] = h;                 // self: plain STS
            if (t + 1 < Tn) st_dsmem(wr_peer[nb], h);     // peer: DSMEM
            g_h1[((size_t)t * 128 + (rank << 6) + cj) * 256 + b0 + cb] = h;
        }
        __syncthreads();                       // bar2: local h visible next step
        if (t + 1 < Tn) cluster_arrive_();
    }
}

// ---------------------------------------------------------------------------
// Layer 1 + FC: cluster of 4 CTAs x 512 threads. Thread = (row 0..127,
// K-quarter): q0/q1 = W_ih lo/hi over h1_t (sbuf, independent -> before wait),
// q2/q3 = W_hh lo/hi over h2_{t-1} (hbuf, after wait). 8 batches (4 f32x2
// pairs). Weights register-resident. Self h plain STS, 3 peer DSMEM stores
// (unconditional; post-loop cluster_wait makes exit safe and feeds the FC).
// smem (floats): hbuf [2][128][12] @0 (3072), sbuf same @3072,
//                gbuf [2][4][128][9] @6144 (9216) -> 15360 f = 61440 B
// ---------------------------------------------------------------------------
#define SMEM1_BYTES (15360 * 4)

__global__ void __cluster_dims__(4, 1, 1) __launch_bounds__(512, 1)
lstm_layer1(const float* __restrict__ Wih, const float* __restrict__ Whh,
            const float* __restrict__ bih, const float* __restrict__ bhh,
            const float* __restrict__ fcW, const float* __restrict__ fcb,
            float* __restrict__ out)
{
    extern __shared__ float sm[];
    float* hbuf = sm;          // [2 par][128 j][12]  (8 batches + pad)
    float* sbuf = sm + 3072;   // [2 par][128 j][12]
    float* gbuf = sm + 6144;   // [2 par][4 q][128 row][9]

    const int tid  = threadIdx.x;
    const int rank = blockIdx.x & 3;
    const int b0   = (blockIdx.x >> 2) * 8;

    const int row     = tid & 127;
    const int quarter = tid >> 7;
    const int grow    = ((row >> 5) << 7) + (rank << 5) + (row & 31);

    float4 w4[16];
    {
        const float4* wsrc = (const float4*)(((quarter < 2) ? Wih : Whh)
                                             + grow * 128 + (quarter & 1) * 64);
        #pragma unroll
        for (int kk = 0; kk < 16; ++kk) w4[kk] = wsrc[kk];
    }
    const unsigned long long bb2 =
        (quarter == 0) ? pk2(bih[grow] + bhh[grow]) : 0ull;

    for (int i = tid; i < 3072; i += 512) hbuf[i] = 0.f;

    // staging map: every thread loads one batch-pair (j, 2*pr)
    const int sj = tid & 127, pr = tid >> 7;
    {
        float2 v = *(const float2*)(g_h1 + (size_t)sj * 256 + b0 + 2 * pr);
        *(float2*)(sbuf + sj * 12 + 2 * pr) = v;
    }
    const int cb = tid >> 5, cj = tid & 31;   // combine map (tid<256)
    const int selfoff = ((rank << 5) + cj) * 12 + cb;
    uint32_t wr_peer[2][3];
    #pragma unroll
    for (int nbv = 0; nbv < 2; ++nbv) {
        uint32_t la = smem_u32(hbuf + nbv * 1536 + selfoff);
        int pi = 0;
        #pragma unroll
        for (int r = 0; r < 4; ++r)
            if (r != rank) wr_peer[nbv][pi++] = mapa_sh(la, r);
    }
    float c = 0.f;
    __syncthreads();
    cluster_arrive_();

    unsigned long long a[4];

    for (int t = 0; t < Tn; ++t) {
        const int par = t & 1, nb = par ^ 1;
        float2 pre = make_float2(0.f, 0.f);
        if (t + 1 < Tn)
            pre = *(const float2*)(g_h1 + ((size_t)(t + 1) * 128 + sj) * 256 + b0 + 2 * pr);

        #pragma unroll
        for (int i = 0; i < 4; ++i) a[i] = bb2;

        const float* src = ((quarter < 2) ? sbuf : hbuf) + par * 1536 + (quarter & 1) * 64 * 12;
        if (quarter < 2) {   // W_ih part: no cross-CTA dependency
            #pragma unroll
            for (int kk = 0; kk < 16; ++kk) {
                float4 wv = w4[kk];
                #pragma unroll
                for (int s = 0; s < 4; ++s) {
                    float w = (s == 0) ? wv.x : (s == 1) ? wv.y : (s == 2) ? wv.z : wv.w;
                    unsigned long long w2 = pk2(w);
                    const float* p = src + (kk * 4 + s) * 12;
                    ulonglong2 h0 = *(const ulonglong2*)(p);
                    ulonglong2 h1 = *(const ulonglong2*)(p + 4);
                    ffma2(a[0], w2, h0.x); ffma2(a[1], w2, h0.y);
                    ffma2(a[2], w2, h1.x); ffma2(a[3], w2, h1.y);
                }
            }
        }
        cluster_wait_();
        if (quarter >= 2) {  // W_hh part: after the h2 exchange
            #pragma unroll
            for (int kk = 0; kk < 16; ++kk) {
                float4 wv = w4[kk];
                #pragma unroll
                for (int s = 0; s < 4; ++s) {
                    float w = (s == 0) ? wv.x : (s == 1) ? wv.y : (s == 2) ? wv.z : wv.w;
                    unsigned long long w2 = pk2(w);
                    const float* p = src + (kk * 4 + s) * 12;
                    ulonglong2 h0 = *(const ulonglong2*)(p);
                    ulonglong2 h1 = *(const ulonglong2*)(p + 4);
                    ffma2(a[0], w2, h0.x); ffma2(a[1], w2, h0.y);
                    ffma2(a[2], w2, h1.x); ffma2(a[3], w2, h1.y);
                }
            }
        }
        {   // gate partials, pitch 9 (conflict-free scalar)
            float* gp = gbuf + ((par * 4 + quarter) * 128 + row) * 9;
            float v0, v1;
            unpk(a[0], v0, v1); gp[0] = v0; gp[1] = v1;
            unpk(a[1], v0, v1); gp[2] = v0; gp[3] = v1;
            unpk(a[2], v0, v1); gp[4] = v0; gp[5] = v1;
            unpk(a[3], v0, v1); gp[6] = v0; gp[7] = v1;
        }
        if (t + 1 < Tn) *(float2*)(sbuf + nb * 1536 + sj * 12 + 2 * pr) = pre;
        __syncthreads();

        if (tid < 256) {
            const float* gq = gbuf + par * 4608;
            float gv[4];
            #pragma unroll
            for (int g = 0; g < 4; ++g) {
                int r = g * 32 + cj;
                gv[g] = gq[r * 9 + cb] + gq[(128 + r) * 9 + cb]
                      + gq[(256 + r) * 9 + cb] + gq[(384 + r) * 9 + cb];
            }
            float ii = sigm(gv[0]), ff = sigm(gv[1]), g = tanh_(gv[2]), oo = sigm(gv[3]);
            c = fmaf(ff, c, ii * g);
            float h = oo * tanh_(c);
            hbuf[nb * 1536 + selfoff] = h;               // self: plain STS
            #pragma unroll
            for (int r = 0; r < 3; ++r) st_dsmem(wr_peer[nb][r], h);
        }
        cluster_arrive_();
    }
    cluster_wait_();   // final h2 exchange complete everywhere; exit-safe

    // FC head: h2_T lives in hbuf[0] ([j][12] batch-major), T even -> buffer 0
    if (rank == 0 && tid < 16) {
        int b = tid >> 1, cl = tid & 1;
        float s = fcb[cl];
        #pragma unroll
        for (int j = 0; j < 128; ++j) s = fmaf(hbuf[j * 12 + b], fcW[cl * 128 + j], s);
        out[(b0 + b) * 2 + cl] = s;
    }
}

// ---------------------------------------------------------------------------
extern "C" void kernel_launch(void* const* d_in, const int* in_sizes, int n_in,
                              void* d_out, int out_size)
{
    const float* x    = (const float*)d_in[0];
    const float* Wih0 = (const float*)d_in[1];
    const float* Whh0 = (const float*)d_in[2];
    const float* bih0 = (const float*)d_in[3];
    const float* bhh0 = (const float*)d_in[4];
    const float* Wih1 = (const float*)d_in[5];
    const float* Whh1 = (const float*)d_in[6];
    const float* bih1 = (const float*)d_in[7];
    const float* bhh1 = (const float*)d_in[8];
    const float* fcW  = (const float*)d_in[9];
    const float* fcb  = (const float*)d_in[10];
    float* out = (float*)d_out;

    cudaFuncSetAttribute(lstm_layer0, cudaFuncAttributeMaxDynamicSharedMemorySize, SMEM0_BYTES);
    cudaFuncSetAttribute(lstm_layer1, cudaFuncAttributeMaxDynamicSharedMemorySize, SMEM1_BYTES);

    lstm_layer0<<<128, 512, SMEM0_BYTES>>>(x, Wih0, Whh0, bih0, bhh0);
    lstm_layer1<<<128, 512, SMEM1_BYTES>>>(Wih1, Whh1, bih1, bhh1, fcW, fcb, out);
}

// round 7
// speedup vs baseline: 1.1898x; 1.1898x over previous
#include <cuda_runtime.h>
#include <cstdint>

#define Tn 2048

// Layer-0 hidden states, layout [T][128 j][256 b] (batch-major innermost)
__device__ float g_h1[(size_t)Tn * 128 * 256];

__device__ __forceinline__ uint32_t smem_u32(const void* p) {
    return (uint32_t)__cvta_generic_to_shared(p);
}
__device__ __forceinline__ void cluster_sync_() {
    asm volatile("barrier.cluster.arrive.aligned;" ::: "memory");
    asm volatile("barrier.cluster.wait.aligned;" ::: "memory");
}
__device__ __forceinline__ uint32_t mapa_sh(uint32_t addr, uint32_t rank) {
    uint32_t r;
    asm("mapa.shared::cluster.u32 %0, %1, %2;" : "=r"(r) : "r"(addr), "r"(rank));
    return r;
}
__device__ __forceinline__ void mbar_init(uint32_t a, uint32_t cnt) {
    asm volatile("mbarrier.init.shared.b64 [%0], %1;" :: "r"(a), "r"(cnt) : "memory");
}
__device__ __forceinline__ void mbar_arm_tx(uint32_t a, uint32_t tx) {
    asm volatile("mbarrier.arrive.expect_tx.shared.b64 _, [%0], %1;"
                 :: "r"(a), "r"(tx) : "memory");
}
// acquire at cluster scope: orders the remote st.async data before our LDS reads
__device__ __forceinline__ void mbar_wait_cl(uint32_t a, uint32_t parity) {
    asm volatile(
        "{\n\t.reg .pred P;\n\t"
        "WL_%=:\n\t"
        "mbarrier.try_wait.parity.acquire.cluster.shared::cta.b64 P, [%0], %1, 0x989680;\n\t"
        "@P bra.uni WD_%=;\n\t"
        "bra.uni WL_%=;\n\t"
        "WD_%=:\n\t}"
        :: "r"(a), "r"(parity) : "memory");
}
// remote store that arrives (complete_tx, 4 bytes) on the target CTA's mbarrier
__device__ __forceinline__ void st_async4(uint32_t addr, float v, uint32_t mbar) {
    asm volatile(
        "st.async.shared::cluster.mbarrier::complete_tx::bytes.b32 [%0], %1, [%2];"
        :: "r"(addr), "r"(__float_as_uint(v)), "r"(mbar) : "memory");
}
__device__ __forceinline__ float sigm(float v) { return 1.0f / (1.0f + __expf(-v)); }
__device__ __forceinline__ float tanh_(float v) { return 2.0f / (1.0f + __expf(-2.0f * v)) - 1.0f; }

// packed f32x2 helpers (SASS FFMA2 — only reachable via PTX fma.rn.f32x2)
__device__ __forceinline__ unsigned long long pk2(float v) {
    unsigned long long r;
    asm("mov.b64 %0, {%1, %1};" : "=l"(r) : "f"(v));
    return r;
}
__device__ __forceinline__ void ffma2(unsigned long long& d, unsigned long long a,
                                      unsigned long long b) {
    asm("fma.rn.f32x2 %0, %1, %2, %0;" : "+l"(d) : "l"(a), "l"(b));
}
__device__ __forceinline__ void unpk(unsigned long long v, float& lo, float& hi) {
    asm("mov.b64 {%0, %1}, %2;" : "=f"(lo), "=f"(hi) : "l"(v));
}

// ---------------------------------------------------------------------------
// Layer 0: cluster of 2 CTAs x 512 threads. Thread = (gate-row 0..255, K-half).
// Half 0 computes the OWN hidden slice (protected by bar2) + x part BEFORE the
// mbarrier wait; half 1 computes the peer slice after the wait. h exchange:
// self slice = plain STS, peer slice = st.async carrying complete_tx into the
// peer's parity mbarrier (tx = 256 floats = 1024 B per phase). No cluster
// barrier in the loop.
// smem floats: [0..3] mbar pair, hbuf [2][128][4] @4, xbuf [2][5][4] @1028,
//              gbuf [2][2][256][5] @1068 -> 6188 floats = 24752 B
// ---------------------------------------------------------------------------
#define SMEM0_BYTES (6188 * 4)

__global__ void __cluster_dims__(2, 1, 1) __launch_bounds__(512, 1)
lstm_layer0(const float* __restrict__ x, const float* __restrict__ Wih,
            const float* __restrict__ Whh, const float* __restrict__ bih,
            const float* __restrict__ bhh)
{
    extern __shared__ float sm[];
    const uint32_t smb = smem_u32(sm);
    float* hbuf = sm + 4;      // [2 par][128 j][4 b]
    float* xbuf = sm + 1028;   // [2 par][5 d][4 b]
    float* gbuf = sm + 1068;   // [2 par][2 half][256 row][5]

    const int tid  = threadIdx.x;
    const int rank = blockIdx.x & 1;
    const int b0   = (blockIdx.x >> 1) * 4;

    const int row    = tid & 255;
    const int half   = tid >> 8;
    const int kslice = rank ^ half;           // half 0 -> own slice
    const int grow   = ((row >> 6) << 7) + (rank << 6) + (row & 63);

    float4 w4[16];
    {
        const float4* wsrc = (const float4*)(Whh + grow * 128 + kslice * 64);
        #pragma unroll
        for (int kk = 0; kk < 16; ++kk) w4[kk] = wsrc[kk];
    }
    unsigned long long wx2[5], bb2;
    {
        float bb = bih[grow] + bhh[grow];
        bb2 = (half == 0) ? pk2(bb) : 0ull;
        #pragma unroll
        for (int d = 0; d < 5; ++d) wx2[d] = pk2(Wih[grow * 5 + d]);
    }

    // mbarriers @ bytes 0 (parity 0-buffer) and 8 (parity 1-buffer); arm both
    if (tid == 0) {
        mbar_init(smb + 0, 1);
        mbar_init(smb + 8, 1);
        mbar_arm_tx(smb + 0, 1024);
        mbar_arm_tx(smb + 8, 1024);
    }
    if (tid < 20) {
        int b = tid / 5, d = tid % 5;
        xbuf[d * 4 + b] = x[((size_t)(b0 + b) * Tn) * 5 + d];
    }

    const int cb = tid >> 6, cj = tid & 63;   // combine map (tid<256)
    const int selfoff = ((rank << 6) + cj) * 4 + cb;
    const uint32_t peer_base = mapa_sh(smb, rank ^ 1);

    cluster_sync_();   // publish mbarrier init/arm before any st.async lands

    // initial h(-1)=0 exchange: self via STS, peer via st.async into mbar[0]
    if (tid < 256) {
        hbuf[selfoff] = 0.f;
        st_async4(peer_base + (4 + selfoff) * 4, 0.f, peer_base + 0);
    }
    __syncthreads();   // self zeros + xbuf visible

    float c = 0.f;

    for (int t = 0; t < Tn; ++t) {
        const int par = t & 1, nb = par ^ 1;
        float pre = 0.f;
        if (tid < 20 && t + 1 < Tn) {
            int b = tid / 5, d = tid % 5;
            pre = x[((size_t)(b0 + b) * Tn + (t + 1)) * 5 + d];
        }
        unsigned long long a01 = bb2, a23 = bb2;
        if (half == 0) {
            const float* xb = xbuf + par * 20;
            #pragma unroll
            for (int d = 0; d < 5; ++d) {
                ffma2(a01, wx2[d], *(const unsigned long long*)(xb + d * 4));
                ffma2(a23, wx2[d], *(const unsigned long long*)(xb + d * 4 + 2));
            }
        }
        const float* hp = hbuf + par * 512 + kslice * 256;
        if (half == 0) {   // own slice: ready via bar2 of previous step
            #pragma unroll
            for (int kk = 0; kk < 16; ++kk) {
                float4 wv = w4[kk];
                #pragma unroll
                for (int s = 0; s < 4; ++s) {
                    float w = (s == 0) ? wv.x : (s == 1) ? wv.y : (s == 2) ? wv.z : wv.w;
                    unsigned long long w2 = pk2(w);
                    ulonglong2 hv = *(const ulonglong2*)(hp + (kk * 4 + s) * 4);
                    ffma2(a01, w2, hv.x);
                    ffma2(a23, w2, hv.y);
                }
            }
        }
        {   // wait for the peer slice of h(t-1); re-arm for t+2
            uint32_t mb = smb + par * 8;
            mbar_wait_cl(mb, (t >> 1) & 1);
            if (tid == 0) mbar_arm_tx(mb, 1024);
        }
        if (half == 1) {   // peer slice
            #pragma unroll
            for (int kk = 0; kk < 16; ++kk) {
                float4 wv = w4[kk];
                #pragma unroll
                for (int s = 0; s < 4; ++s) {
                    float w = (s == 0) ? wv.x : (s == 1) ? wv.y : (s == 2) ? wv.z : wv.w;
                    unsigned long long w2 = pk2(w);
                    ulonglong2 hv = *(const ulonglong2*)(hp + (kk * 4 + s) * 4);
                    ffma2(a01, w2, hv.x);
                    ffma2(a23, w2, hv.y);
                }
            }
        }
        {   // gate partials, pitch 5 (conflict-free)
            float* gp = gbuf + ((par * 2 + half) * 256 + row) * 5;
            float g0, g1, g2, g3;
            unpk(a01, g0, g1); unpk(a23, g2, g3);
            gp[0] = g0; gp[1] = g1; gp[2] = g2; gp[3] = g3;
        }
        if (tid < 20 && t + 1 < Tn) {
            int b = tid / 5, d = tid % 5;
            xbuf[nb * 20 + d * 4 + b] = pre;
        }
        __syncthreads();                       // bar1: gbuf ready
        if (tid < 256) {
            const float* g0p = gbuf + par * 2560;
            const float* g1p = g0p + 1280;
            float gi = g0p[cj * 5 + cb]         + g1p[cj * 5 + cb];
            float gf = g0p[(64 + cj) * 5 + cb]  + g1p[(64 + cj) * 5 + cb];
            float gg = g0p[(128 + cj) * 5 + cb] + g1p[(128 + cj) * 5 + cb];
            float go = g0p[(192 + cj) * 5 + cb] + g1p[(192 + cj) * 5 + cb];
            float ii = sigm(gi), ff = sigm(gf), g = tanh_(gg), oo = sigm(go);
            c = fmaf(ff, c, ii * g);
            float h = oo * tanh_(c);
            hbuf[nb * 512 + selfoff] = h;                         // self: STS
            st_async4(peer_base + (4 + nb * 512 + selfoff) * 4,   // peer: async
                      h, peer_base + nb * 8);
            g_h1[((size_t)t * 128 + (rank << 6) + cj) * 256 + b0 + cb] = h;
        }
        __syncthreads();                       // bar2: self h for next half-0
    }
    // consume the final exchange (also proves our last stores landed at the
    // peer before it exits — exit safety without any cluster barrier)
    mbar_wait_cl(smb + 0, (Tn >> 1) & 1);
}

// ---------------------------------------------------------------------------
// Layer 1 + FC: cluster of 4 CTAs x 512 threads. Thread = (row 0..127,
// K-quarter): q0/q1 = W_ih lo/hi over h1_t (sbuf, computed BEFORE the wait),
// q2/q3 = W_hh lo/hi over h2_{t-1} (hbuf, after the wait). h2 exchange: every
// rank (incl. self) receives each 32-j slice via st.async; the parity mbarrier
// expects tx = 4 x 1024 B = 4096 B. One __syncthreads per step (gbuf).
// smem floats: [0..3] mbar pair, hbuf [2][128][12] @4, sbuf same @3076,
//              gbuf [2][4][128][9] @6148 -> 15364 floats = 61456 B
// ---------------------------------------------------------------------------
#define SMEM1_BYTES (15364 * 4)

__global__ void __cluster_dims__(4, 1, 1) __launch_bounds__(512, 1)
lstm_layer1(const float* __restrict__ Wih, const float* __restrict__ Whh,
            const float* __restrict__ bih, const float* __restrict__ bhh,
            const float* __restrict__ fcW, const float* __restrict__ fcb,
            float* __restrict__ out)
{
    extern __shared__ float sm[];
    const uint32_t smb = smem_u32(sm);
    float* hbuf = sm + 4;      // [2 par][128 j][12] (8 batches + pad)
    float* sbuf = sm + 3076;   // [2 par][128 j][12]
    float* gbuf = sm + 6148;   // [2 par][4 q][128 row][9]

    const int tid  = threadIdx.x;
    const int rank = blockIdx.x & 3;
    const int b0   = (blockIdx.x >> 2) * 8;

    const int row     = tid & 127;
    const int quarter = tid >> 7;
    const int grow    = ((row >> 5) << 7) + (rank << 5) + (row & 31);

    float4 w4[16];
    {
        const float4* wsrc = (const float4*)(((quarter < 2) ? Wih : Whh)
                                             + grow * 128 + (quarter & 1) * 64);
        #pragma unroll
        for (int kk = 0; kk < 16; ++kk) w4[kk] = wsrc[kk];
    }
    const unsigned long long bb2 =
        (quarter == 0) ? pk2(bih[grow] + bhh[grow]) : 0ull;

    if (tid == 0) {
        mbar_init(smb + 0, 1);
        mbar_init(smb + 8, 1);
        mbar_arm_tx(smb + 0, 4096);
        mbar_arm_tx(smb + 8, 4096);
    }

    // h1 staging map (coalesced float2 per thread)
    const int sj = tid & 127, pr = tid >> 7;
    {
        float2 v = *(const float2*)(g_h1 + (size_t)sj * 256 + b0 + 2 * pr);
        *(float2*)(sbuf + sj * 12 + 2 * pr) = v;
    }
    const int cb = tid >> 5, cj = tid & 31;   // combine map (tid<256)
    const int selfoff = ((rank << 5) + cj) * 12 + cb;
    uint32_t base[4];
    #pragma unroll
    for (int r = 0; r < 4; ++r) base[r] = mapa_sh(smb, r);

    cluster_sync_();   // publish mbarrier init/arm

    // initial h2(-1)=0 exchange to every rank's buffer 0
    if (tid < 256) {
        #pragma unroll
        for (int r = 0; r < 4; ++r)
            st_async4(base[r] + (4 + selfoff) * 4, 0.f, base[r] + 0);
    }
    __syncthreads();   // sbuf staging visible

    float c = 0.f;
    unsigned long long a[4];

    for (int t = 0; t < Tn; ++t) {
        const int par = t & 1, nb = par ^ 1;
        float2 pre = make_float2(0.f, 0.f);
        if (t + 1 < Tn)
            pre = *(const float2*)(g_h1 + ((size_t)(t + 1) * 128 + sj) * 256 + b0 + 2 * pr);

        #pragma unroll
        for (int i = 0; i < 4; ++i) a[i] = bb2;

        const float* src = ((quarter < 2) ? sbuf : hbuf) + par * 1536 + (quarter & 1) * 768;
        if (quarter < 2) {   // W_ih part: no cross-CTA dependency
            #pragma unroll
            for (int kk = 0; kk < 16; ++kk) {
                float4 wv = w4[kk];
                #pragma unroll
                for (int s = 0; s < 4; ++s) {
                    float w = (s == 0) ? wv.x : (s == 1) ? wv.y : (s == 2) ? wv.z : wv.w;
                    unsigned long long w2 = pk2(w);
                    const float* p = src + (kk * 4 + s) * 12;
                    ulonglong2 h0 = *(const ulonglong2*)(p);
                    ulonglong2 h1 = *(const ulonglong2*)(p + 4);
                    ffma2(a[0], w2, h0.x); ffma2(a[1], w2, h0.y);
                    ffma2(a[2], w2, h1.x); ffma2(a[3], w2, h1.y);
                }
            }
        }
        {   // wait for the full h2(t-1); re-arm for t+2
            uint32_t mb = smb + par * 8;
            mbar_wait_cl(mb, (t >> 1) & 1);
            if (tid == 0) mbar_arm_tx(mb, 4096);
        }
        if (quarter >= 2) {  // W_hh part: after the h2 exchange
            #pragma unroll
            for (int kk = 0; kk < 16; ++kk) {
                float4 wv = w4[kk];
                #pragma unroll
                for (int s = 0; s < 4; ++s) {
                    float w = (s == 0) ? wv.x : (s == 1) ? wv.y : (s == 2) ? wv.z : wv.w;
                    unsigned long long w2 = pk2(w);
                    const float* p = src + (kk * 4 + s) * 12;
                    ulonglong2 h0 = *(const ulonglong2*)(p);
                    ulonglong2 h1 = *(const ulonglong2*)(p + 4);
                    ffma2(a[0], w2, h0.x); ffma2(a[1], w2, h0.y);
                    ffma2(a[2], w2, h1.x); ffma2(a[3], w2, h1.y);
                }
            }
        }
        {   // gate partials, pitch 9 (conflict-free scalar)
            float* gp = gbuf + ((par * 4 + quarter) * 128 + row) * 9;
            float v0, v1;
            unpk(a[0], v0, v1); gp[0] = v0; gp[1] = v1;
            unpk(a[1], v0, v1); gp[2] = v0; gp[3] = v1;
            unpk(a[2], v0, v1); gp[4] = v0; gp[5] = v1;
            unpk(a[3], v0, v1); gp[6] = v0; gp[7] = v1;
        }
        if (t + 1 < Tn) *(float2*)(sbuf + nb * 1536 + sj * 12 + 2 * pr) = pre;
        __syncthreads();   // bar1: gbuf + sbuf[nb] ready

        if (tid < 256) {
            const float* gq = gbuf + par * 4608;
            float gv[4];
            #pragma unroll
            for (int g = 0; g < 4; ++g) {
                int r = g * 32 + cj;
                gv[g] = gq[r * 9 + cb] + gq[(128 + r) * 9 + cb]
                      + gq[(256 + r) * 9 + cb] + gq[(384 + r) * 9 + cb];
            }
            float ii = sigm(gv[0]), ff = sigm(gv[1]), g = tanh_(gv[2]), oo = sigm(gv[3]);
            c = fmaf(ff, c, ii * g);
            float h = oo * tanh_(c);
            uint32_t dat = (4 + nb * 1536 + selfoff) * 4;
            uint32_t mbo = nb * 8;
            #pragma unroll
            for (int r = 0; r < 4; ++r)
                st_async4(base[r] + dat, h, base[r] + mbo);
        }
    }
    // consume the final exchange (buffer 0, T even) — also exit safety
    mbar_wait_cl(smb + 0, (Tn >> 1) & 1);

    // FC head: full final h2 lives in hbuf buffer 0 ([j][12] batch-major)
    if (rank == 0 && tid < 16) {
        int b = tid >> 1, cl = tid & 1;
        float s = fcb[cl];
        #pragma unroll
        for (int j = 0; j < 128; ++j) s = fmaf(hbuf[j * 12 + b], fcW[cl * 128 + j], s);
        out[(b0 + b) * 2 + cl] = s;
    }
}

// ---------------------------------------------------------------------------
extern "C" void kernel_launch(void* const* d_in, const int* in_sizes, int n_in,
                              void* d_out, int out_size)
{
    const float* x    = (const float*)d_in[0];
    const float* Wih0 = (const float*)d_in[1];
    const float* Whh0 = (const float*)d_in[2];
    const float* bih0 = (const float*)d_in[3];
    const float* bhh0 = (const float*)d_in[4];
    const float* Wih1 = (const float*)d_in[5];
    const float* Whh1 = (const float*)d_in[6];
    const float* bih1 = (const float*)d_in[7];
    const float* bhh1 = (const float*)d_in[8];
    const float* fcW  = (const float*)d_in[9];
    const float* fcb  = (const float*)d_in[10];
    float* out = (float*)d_out;

    cudaFuncSetAttribute(lstm_layer0, cudaFuncAttributeMaxDynamicSharedMemorySize, SMEM0_BYTES);
    cudaFuncSetAttribute(lstm_layer1, cudaFuncAttributeMaxDynamicSharedMemorySize, SMEM1_BYTES);

    lstm_layer0<<<128, 512, SMEM0_BYTES>>>(x, Wih0, Whh0, bih0, bhh0);
    lstm_layer1<<<128, 512, SMEM1_BYTES>>>(Wih1, Whh1, bih1, bhh1, fcW, fcb, out);
}

// round 8
// speedup vs baseline: 1.3016x; 1.0940x over previous
#include <cuda_runtime.h>
#include <cstdint>

#define Tn 2048

// Layer-0 hidden states, layout [T][128 j][256 b] (batch-major innermost)
__device__ float g_h1[(size_t)Tn * 128 * 256];

__device__ __forceinline__ uint32_t smem_u32(const void* p) {
    return (uint32_t)__cvta_generic_to_shared(p);
}
__device__ __forceinline__ void cluster_sync_() {
    asm volatile("barrier.cluster.arrive.aligned;" ::: "memory");
    asm volatile("barrier.cluster.wait.aligned;" ::: "memory");
}
__device__ __forceinline__ uint32_t mapa_sh(uint32_t addr, uint32_t rank) {
    uint32_t r;
    asm("mapa.shared::cluster.u32 %0, %1, %2;" : "=r"(r) : "r"(addr), "r"(rank));
    return r;
}
__device__ __forceinline__ void mbar_init(uint32_t a, uint32_t cnt) {
    asm volatile("mbarrier.init.shared.b64 [%0], %1;" :: "r"(a), "r"(cnt) : "memory");
}
__device__ __forceinline__ void mbar_arm_tx(uint32_t a, uint32_t tx) {
    asm volatile("mbarrier.arrive.expect_tx.shared.b64 _, [%0], %1;"
                 :: "r"(a), "r"(tx) : "memory");
}
// acquire at cluster scope: orders arrived bulk-copy data before our LDS reads
__device__ __forceinline__ void mbar_wait_cl(uint32_t a, uint32_t parity) {
    asm volatile(
        "{\n\t.reg .pred P;\n\t"
        "WL_%=:\n\t"
        "mbarrier.try_wait.parity.acquire.cluster.shared::cta.b64 P, [%0], %1, 0x989680;\n\t"
        "@P bra.uni WD_%=;\n\t"
        "bra.uni WL_%=;\n\t"
        "WD_%=:\n\t}"
        :: "r"(a), "r"(parity) : "memory");
}
// DSMEM bulk copy: smem(cta) -> smem(cluster), complete_tx on target mbarrier
__device__ __forceinline__ void bulk_dsmem(uint32_t dst, uint32_t src,
                                           uint32_t bytes, uint32_t mbar) {
    asm volatile(
        "cp.async.bulk.shared::cluster.shared::cta.mbarrier::complete_tx::bytes "
        "[%0], [%1], %2, [%3];"
        :: "r"(dst), "r"(src), "r"(bytes), "r"(mbar) : "memory");
}
__device__ __forceinline__ void fence_async_() {
    asm volatile("fence.proxy.async.shared::cta;" ::: "memory");
}
__device__ __forceinline__ float sigm(float v) { return 1.0f / (1.0f + __expf(-v)); }
__device__ __forceinline__ float tanh_(float v) { return 2.0f / (1.0f + __expf(-2.0f * v)) - 1.0f; }

// packed f32x2 helpers (SASS FFMA2 — only reachable via PTX fma.rn.f32x2)
__device__ __forceinline__ unsigned long long pk2(float v) {
    unsigned long long r;
    asm("mov.b64 %0, {%1, %1};" : "=l"(r) : "f"(v));
    return r;
}
__device__ __forceinline__ void ffma2(unsigned long long& d, unsigned long long a,
                                      unsigned long long b) {
    asm("fma.rn.f32x2 %0, %1, %2, %0;" : "+l"(d) : "l"(a), "l"(b));
}
__device__ __forceinline__ void unpk(unsigned long long v, float& lo, float& hi) {
    asm("mov.b64 {%0, %1}, %2;" : "=f"(lo), "=f"(hi) : "l"(v));
}

// ---------------------------------------------------------------------------
// Layer 0: cluster of 2 CTAs x 512 threads, 4 batches/cluster. Thread =
// (gate-row 0..255, K-half). Half 0 = own hidden slice (pre-wait, bar2-
// protected), half 1 = peer slice (post-wait). Exchange: self slice via STS,
// peer slice via 8x128B bulk copies (one per combine warp) with complete_tx
// into the peer's parity mbarrier (tx = 1024 B).
// smem floats: mbar[4] @0, hbuf [2][128][4] @4, xbuf [2][5][4] @1028,
//              gbuf [2][2][256][5] @1068 -> 6188 floats
// ---------------------------------------------------------------------------
#define SMEM0_BYTES (6188 * 4)

__global__ void __cluster_dims__(2, 1, 1) __launch_bounds__(512, 1)
lstm_layer0(const float* __restrict__ x, const float* __restrict__ Wih,
            const float* __restrict__ Whh, const float* __restrict__ bih,
            const float* __restrict__ bhh)
{
    extern __shared__ float sm[];
    const uint32_t smb = smem_u32(sm);
    float* hbuf = sm + 4;      // [2 par][128 j][4 b] (j*4+b linear)
    float* xbuf = sm + 1028;   // [2 par][5 d][4 b]
    float* gbuf = sm + 1068;   // [2 par][2 half][256 row][5]

    const int tid  = threadIdx.x;
    const int rank = blockIdx.x & 1;
    const int b0   = (blockIdx.x >> 1) * 4;

    const int row    = tid & 255;
    const int half   = tid >> 8;
    const int kslice = rank ^ half;           // half 0 -> own slice
    const int grow   = ((row >> 6) << 7) + (rank << 6) + (row & 63);

    float4 w4[16];
    {
        const float4* wsrc = (const float4*)(Whh + grow * 128 + kslice * 64);
        #pragma unroll
        for (int kk = 0; kk < 16; ++kk) w4[kk] = wsrc[kk];
    }
    unsigned long long wx2[5], bb2;
    {
        float bb = bih[grow] + bhh[grow];
        bb2 = (half == 0) ? pk2(bb) : 0ull;
        #pragma unroll
        for (int d = 0; d < 5; ++d) wx2[d] = pk2(Wih[grow * 5 + d]);
    }

    if (tid == 0) {
        mbar_init(smb + 0, 1);
        mbar_init(smb + 8, 1);
        mbar_arm_tx(smb + 0, 1024);
        mbar_arm_tx(smb + 8, 1024);
    }
    for (int i = tid; i < 1024; i += 512) hbuf[i] = 0.f;
    if (tid < 20) {
        int b = tid / 5, d = tid % 5;
        xbuf[d * 4 + b] = x[((size_t)(b0 + b) * Tn) * 5 + d];
    }

    const int cb = tid & 3, cj = (tid >> 2) & 63;   // combine map (tid<256)
    const uint32_t peer = mapa_sh(smb, rank ^ 1);

    __syncthreads();
    cluster_sync_();   // mbarriers armed + hbuf zeroed cluster-wide
    if (tid == 0) {    // initial h(-1)=0 exchange: ship zeroed own slice
        fence_async_();
        uint32_t off = (4 + rank * 256) * 4;
        bulk_dsmem(peer + off, smb + off, 1024, peer + 0);
    }

    float c = 0.f;

    for (int t = 0; t < Tn; ++t) {
        const int par = t & 1, nb = par ^ 1;
        float pre = 0.f;
        if (tid < 20 && t + 1 < Tn) {
            int b = tid / 5, d = tid % 5;
            pre = x[((size_t)(b0 + b) * Tn + (t + 1)) * 5 + d];
        }
        unsigned long long a01 = bb2, a23 = bb2;
        if (half == 0) {
            const float* xb = xbuf + par * 20;
            #pragma unroll
            for (int d = 0; d < 5; ++d) {
                ffma2(a01, wx2[d], *(const unsigned long long*)(xb + d * 4));
                ffma2(a23, wx2[d], *(const unsigned long long*)(xb + d * 4 + 2));
            }
        }
        const float* hp = hbuf + par * 512 + kslice * 256;
        if (half == 0) {   // own slice: ready via bar2 of previous step
            #pragma unroll
            for (int kk = 0; kk < 16; ++kk) {
                float4 wv = w4[kk];
                #pragma unroll
                for (int s = 0; s < 4; ++s) {
                    float w = (s == 0) ? wv.x : (s == 1) ? wv.y : (s == 2) ? wv.z : wv.w;
                    unsigned long long w2 = pk2(w);
                    ulonglong2 hv = *(const ulonglong2*)(hp + (kk * 4 + s) * 4);
                    ffma2(a01, w2, hv.x);
                    ffma2(a23, w2, hv.y);
                }
            }
        }
        {   // wait for the peer slice of h(t-1); re-arm for t+2
            uint32_t mb = smb + par * 8;
            mbar_wait_cl(mb, (t >> 1) & 1);
            if (tid == 0) mbar_arm_tx(mb, 1024);
        }
        if (half == 1) {   // peer slice (delivered by bulk copies)
            #pragma unroll
            for (int kk = 0; kk < 16; ++kk) {
                float4 wv = w4[kk];
                #pragma unroll
                for (int s = 0; s < 4; ++s) {
                    float w = (s == 0) ? wv.x : (s == 1) ? wv.y : (s == 2) ? wv.z : wv.w;
                    unsigned long long w2 = pk2(w);
                    ulonglong2 hv = *(const ulonglong2*)(hp + (kk * 4 + s) * 4);
                    ffma2(a01, w2, hv.x);
                    ffma2(a23, w2, hv.y);
                }
            }
        }
        {   // gate partials, pitch 5 (conflict-free)
            float* gp = gbuf + ((par * 2 + half) * 256 + row) * 5;
            float g0, g1, g2, g3;
            unpk(a01, g0, g1); unpk(a23, g2, g3);
            gp[0] = g0; gp[1] = g1; gp[2] = g2; gp[3] = g3;
        }
        if (tid < 20 && t + 1 < Tn) {
            int b = tid / 5, d = tid % 5;
            xbuf[nb * 20 + d * 4 + b] = pre;
        }
        __syncthreads();                       // bar1: gbuf ready
        if (tid < 256) {
            const float* g0p = gbuf + par * 2560;
            const float* g1p = g0p + 1280;
            float gi = g0p[cj * 5 + cb]         + g1p[cj * 5 + cb];
            float gf = g0p[(64 + cj) * 5 + cb]  + g1p[(64 + cj) * 5 + cb];
            float gg = g0p[(128 + cj) * 5 + cb] + g1p[(128 + cj) * 5 + cb];
            float go = g0p[(192 + cj) * 5 + cb] + g1p[(192 + cj) * 5 + cb];
            float ii = sigm(gi), ff = sigm(gf), g = tanh_(gg), oo = sigm(go);
            c = fmaf(ff, c, ii * g);
            float h = oo * tanh_(c);
            hbuf[nb * 512 + rank * 256 + tid] = h;   // self slice, contiguous STS
            g_h1[((size_t)t * 128 + (rank << 6) + cj) * 256 + b0 + cb] = h;
            __syncwarp();
            if ((tid & 31) == 0) {                   // 1 bulk copy per warp region
                fence_async_();
                uint32_t off = (4 + nb * 512 + rank * 256 + (tid & 224)) * 4;
                bulk_dsmem(peer + off, smb + off, 128, peer + nb * 8);
            }
        }
        __syncthreads();                       // bar2: self h for next half-0
    }
    // consume the final exchange (exit safety without any cluster barrier)
    mbar_wait_cl(smb + 0, (Tn >> 1) & 1);
}

// ---------------------------------------------------------------------------
// Layer 1 + FC: cluster of 4 CTAs x 512 threads, 8 batches/cluster. Thread =
// (row 0..127, K-quarter): q0/q1 = W_ih lo/hi over h1_t (pre-wait), q2/q3 =
// W_hh lo/hi over h2_{t-1} (post-wait). Exchange: combine writes h into a
// parity-doubled stage; each combine warp ships its 128B region to ALL 4
// ranks (self included) via bulk copies -> tx = 4 x 1024 B = 4096 B, no
// second __syncthreads needed.
// smem floats: mbar[4] @0, hbuf [2][128][8] @4, sbuf [2][128][8] @2052,
//              stage [2][256] @4100, gbuf [2][4][128][9] @4612 -> 13828 floats
// ---------------------------------------------------------------------------
#define SMEM1_BYTES (13828 * 4)

__global__ void __cluster_dims__(4, 1, 1) __launch_bounds__(512, 1)
lstm_layer1(const float* __restrict__ Wih, const float* __restrict__ Whh,
            const float* __restrict__ bih, const float* __restrict__ bhh,
            const float* __restrict__ fcW, const float* __restrict__ fcb,
            float* __restrict__ out)
{
    extern __shared__ float sm[];
    const uint32_t smb = smem_u32(sm);
    float* hbuf  = sm + 4;     // [2 par][128 j][8 b] (j*8+b linear)
    float* sbuf  = sm + 2052;  // [2 par][128 j][8 b]
    float* stage = sm + 4100;  // [2 par][256] outgoing h slice
    float* gbuf  = sm + 4612;  // [2 par][4 q][128 row][9]

    const int tid  = threadIdx.x;
    const int rank = blockIdx.x & 3;
    const int b0   = (blockIdx.x >> 2) * 8;

    const int row     = tid & 127;
    const int quarter = tid >> 7;
    const int grow    = ((row >> 5) << 7) + (rank << 5) + (row & 31);

    float4 w4[16];
    {
        const float4* wsrc = (const float4*)(((quarter < 2) ? Wih : Whh)
                                             + grow * 128 + (quarter & 1) * 64);
        #pragma unroll
        for (int kk = 0; kk < 16; ++kk) w4[kk] = wsrc[kk];
    }
    const unsigned long long bb2 =
        (quarter == 0) ? pk2(bih[grow] + bhh[grow]) : 0ull;

    if (tid == 0) {
        mbar_init(smb + 0, 1);
        mbar_init(smb + 8, 1);
        mbar_arm_tx(smb + 0, 4096);
        mbar_arm_tx(smb + 8, 4096);
    }
    for (int i = tid; i < 2048; i += 512) hbuf[i]  = 0.f;
    for (int i = tid; i < 512;  i += 512) stage[i] = 0.f;

    // h1 staging map (float2 per thread fully covers sbuf buffer 0)
    const int sj = tid >> 2, pq = tid & 3;
    {
        float2 v = *(const float2*)(g_h1 + (size_t)sj * 256 + b0 + pq * 2);
        *(float2*)(sbuf + sj * 8 + pq * 2) = v;
    }
    const int cb = tid & 7, cj = (tid >> 3) & 31;   // combine map (tid<256)
    uint32_t base[4];
    #pragma unroll
    for (int r = 0; r < 4; ++r) base[r] = mapa_sh(smb, r);

    __syncthreads();
    cluster_sync_();   // mbarriers armed + buffers zeroed cluster-wide
    if (tid < 4) {     // initial h2(-1)=0 exchange: ship zeroed stage0 slice
        fence_async_();
        bulk_dsmem(base[tid] + (4 + rank * 256) * 4, smb + 4100 * 4,
                   1024, base[tid] + 0);
    }

    float c = 0.f;
    unsigned long long a[4];

    for (int t = 0; t < Tn; ++t) {
        const int par = t & 1, nb = par ^ 1;
        float2 pre = make_float2(0.f, 0.f);
        if (t + 1 < Tn)
            pre = *(const float2*)(g_h1 + ((size_t)(t + 1) * 128 + sj) * 256 + b0 + pq * 2);

        #pragma unroll
        for (int i = 0; i < 4; ++i) a[i] = bb2;

        const float* src = ((quarter < 2) ? sbuf : hbuf) + par * 1024 + (quarter & 1) * 512;
        if (quarter < 2) {   // W_ih part: no cross-CTA dependency
            #pragma unroll
            for (int kk = 0; kk < 16; ++kk) {
                float4 wv = w4[kk];
                #pragma unroll
                for (int s = 0; s < 4; ++s) {
                    float w = (s == 0) ? wv.x : (s == 1) ? wv.y : (s == 2) ? wv.z : wv.w;
                    unsigned long long w2 = pk2(w);
                    const float* p = src + (kk * 4 + s) * 8;
                    ulonglong2 h0 = *(const ulonglong2*)(p);
                    ulonglong2 h1 = *(const ulonglong2*)(p + 4);
                    ffma2(a[0], w2, h0.x); ffma2(a[1], w2, h0.y);
                    ffma2(a[2], w2, h1.x); ffma2(a[3], w2, h1.y);
                }
            }
        }
        {   // wait for the full h2(t-1); re-arm for t+2
            uint32_t mb = smb + par * 8;
            mbar_wait_cl(mb, (t >> 1) & 1);
            if (tid == 0) mbar_arm_tx(mb, 4096);
        }
        if (quarter >= 2) {  // W_hh part: after the h2 exchange
            #pragma unroll
            for (int kk = 0; kk < 16; ++kk) {
                float4 wv = w4[kk];
                #pragma unroll
                for (int s = 0; s < 4; ++s) {
                    float w = (s == 0) ? wv.x : (s == 1) ? wv.y : (s == 2) ? wv.z : wv.w;
                    unsigned long long w2 = pk2(w);
                    const float* p = src + (kk * 4 + s) * 8;
                    ulonglong2 h0 = *(const ulonglong2*)(p);
                    ulonglong2 h1 = *(const ulonglong2*)(p + 4);
                    ffma2(a[0], w2, h0.x); ffma2(a[1], w2, h0.y);
                    ffma2(a[2], w2, h1.x); ffma2(a[3], w2, h1.y);
                }
            }
        }
        {   // gate partials, pitch 9 (conflict-free scalar)
            float* gp = gbuf + ((par * 4 + quarter) * 128 + row) * 9;
            float v0, v1;
            unpk(a[0], v0, v1); gp[0] = v0; gp[1] = v1;
            unpk(a[1], v0, v1); gp[2] = v0; gp[3] = v1;
            unpk(a[2], v0, v1); gp[4] = v0; gp[5] = v1;
            unpk(a[3], v0, v1); gp[6] = v0; gp[7] = v1;
        }
        if (t + 1 < Tn) *(float2*)(sbuf + nb * 1024 + sj * 8 + pq * 2) = pre;
        __syncthreads();   // bar1: gbuf + sbuf[nb] ready

        if (tid < 256) {
            const float* gq = gbuf + par * 4608;
            float gv[4];
            #pragma unroll
            for (int g = 0; g < 4; ++g) {
                int r = g * 32 + cj;
                gv[g] = gq[r * 9 + cb] + gq[(128 + r) * 9 + cb]
                      + gq[(256 + r) * 9 + cb] + gq[(384 + r) * 9 + cb];
            }
            float ii = sigm(gv[0]), ff = sigm(gv[1]), g = tanh_(gv[2]), oo = sigm(gv[3]);
            c = fmaf(ff, c, ii * g);
            float h = oo * tanh_(c);
            stage[nb * 256 + tid] = h;          // contiguous per-warp regions
            __syncwarp();
            if ((tid & 31) < 4) {               // 4 copies per warp: one per rank
                int dr = tid & 31;
                fence_async_();
                uint32_t dsto = (4 + nb * 1024 + rank * 256 + (tid & 224)) * 4;
                uint32_t srco = (4100 + nb * 256 + (tid & 224)) * 4;
                bulk_dsmem(base[dr] + dsto, smb + srco, 128, base[dr] + nb * 8);
            }
        }
    }
    // consume the final exchange (buffer 0, T even) — also exit safety
    mbar_wait_cl(smb + 0, (Tn >> 1) & 1);

    // FC head: full final h2 in hbuf buffer 0 ([j][8] batch-major, async-delivered)
    if (rank == 0 && tid < 16) {
        int b = tid >> 1, cl = tid & 1;
        float s = fcb[cl];
        #pragma unroll
        for (int j = 0; j < 128; ++j) s = fmaf(hbuf[j * 8 + b], fcW[cl * 128 + j], s);
        out[(b0 + b) * 2 + cl] = s;
    }
}

// ---------------------------------------------------------------------------
extern "C" void kernel_launch(void* const* d_in, const int* in_sizes, int n_in,
                              void* d_out, int out_size)
{
    const float* x    = (const float*)d_in[0];
    const float* Wih0 = (const float*)d_in[1];
    const float* Whh0 = (const float*)d_in[2];
    const float* bih0 = (const float*)d_in[3];
    const float* bhh0 = (const float*)d_in[4];
    const float* Wih1 = (const float*)d_in[5];
    const float* Whh1 = (const float*)d_in[6];
    const float* bih1 = (const float*)d_in[7];
    const float* bhh1 = (const float*)d_in[8];
    const float* fcW  = (const float*)d_in[9];
    const float* fcb  = (const float*)d_in[10];
    float* out = (float*)d_out;

    cudaFuncSetAttribute(lstm_layer0, cudaFuncAttributeMaxDynamicSharedMemorySize, SMEM0_BYTES);
    cudaFuncSetAttribute(lstm_layer1, cudaFuncAttributeMaxDynamicSharedMemorySize, SMEM1_BYTES);

    lstm_layer0<<<128, 512, SMEM0_BYTES>>>(x, Wih0, Whh0, bih0, bhh0);
    lstm_layer1<<<128, 512, SMEM1_BYTES>>>(Wih1, Whh1, bih1, bhh1, fcW, fcb, out);
}

// round 9
// speedup vs baseline: 1.5861x; 1.2185x over previous
#include <cuda_runtime.h>
#include <cstdint>

#define Tn 2048

// Layer-0 hidden states, layout [T][128 j][256 b] (batch-major innermost)
__device__ float g_h1[(size_t)Tn * 128 * 256];

__device__ __forceinline__ uint32_t smem_u32(const void* p) {
    return (uint32_t)__cvta_generic_to_shared(p);
}
__device__ __forceinline__ void cluster_sync_() {
    asm volatile("barrier.cluster.arrive.aligned;" ::: "memory");
    asm volatile("barrier.cluster.wait.aligned;" ::: "memory");
}
__device__ __forceinline__ uint32_t mapa_sh(uint32_t addr, uint32_t rank) {
    uint32_t r;
    asm("mapa.shared::cluster.u32 %0, %1, %2;" : "=r"(r) : "r"(addr), "r"(rank));
    return r;
}
__device__ __forceinline__ void mbar_init(uint32_t a, uint32_t cnt) {
    asm volatile("mbarrier.init.shared.b64 [%0], %1;" :: "r"(a), "r"(cnt) : "memory");
}
__device__ __forceinline__ void mbar_arm_tx(uint32_t a, uint32_t tx) {
    asm volatile("mbarrier.arrive.expect_tx.shared.b64 _, [%0], %1;"
                 :: "r"(a), "r"(tx) : "memory");
}
// acquire at cluster scope: orders arrived bulk-copy data before our LDS reads
__device__ __forceinline__ void mbar_wait_cl(uint32_t a, uint32_t parity) {
    asm volatile(
        "{\n\t.reg .pred P;\n\t"
        "WL_%=:\n\t"
        "mbarrier.try_wait.parity.acquire.cluster.shared::cta.b64 P, [%0], %1, 0x989680;\n\t"
        "@P bra.uni WD_%=;\n\t"
        "bra.uni WL_%=;\n\t"
        "WD_%=:\n\t}"
        :: "r"(a), "r"(parity) : "memory");
}
// DSMEM bulk copy: smem(cta) -> smem(cluster), complete_tx on target mbarrier
__device__ __forceinline__ void bulk_dsmem(uint32_t dst, uint32_t src,
                                           uint32_t bytes, uint32_t mbar) {
    asm volatile(
        "cp.async.bulk.shared::cluster.shared::cta.mbarrier::complete_tx::bytes "
        "[%0], [%1], %2, [%3];"
        :: "r"(dst), "r"(src), "r"(bytes), "r"(mbar) : "memory");
}
__device__ __forceinline__ void fence_async_() {
    asm volatile("fence.proxy.async.shared::cta;" ::: "memory");
}
__device__ __forceinline__ float sigm(float v) { return 1.0f / (1.0f + __expf(-v)); }
__device__ __forceinline__ float tanh_(float v) { return 2.0f / (1.0f + __expf(-2.0f * v)) - 1.0f; }

// packed f32x2 helpers (SASS FFMA2 — only reachable via PTX fma.rn.f32x2)
__device__ __forceinline__ unsigned long long pk2(float v) {
    unsigned long long r;
    asm("mov.b64 %0, {%1, %1};" : "=l"(r) : "f"(v));
    return r;
}
__device__ __forceinline__ void ffma2(unsigned long long& d, unsigned long long a,
                                      unsigned long long b) {
    asm("fma.rn.f32x2 %0, %1, %2, %0;" : "+l"(d) : "l"(a), "l"(b));
}
__device__ __forceinline__ void unpk(unsigned long long v, float& lo, float& hi) {
    asm("mov.b64 {%0, %1}, %2;" : "=f"(lo), "=f"(hi) : "l"(v));
}
__device__ __forceinline__ float sel4(float4 v, int s) {
    return (s == 0) ? v.x : (s == 1) ? v.y : (s == 2) ? v.z : v.w;
}

// ---------------------------------------------------------------------------
// Layer 0: cluster of 2 CTAs x 512 threads, 4 batches/cluster. Thread =
// (row-pair rp 0..127 -> rows rp & rp+128, K-segment seg 0..3 of 32 j each).
// Segs 0,1 = own hidden slice (pre-wait), segs 2,3 = peer slice (post-wait).
// Each h load feeds TWO rows -> broadcast LDS wavefronts halved.
// Exchange: self slice via STS (bar2-protected), peer via 8x128B bulk copies
// with complete_tx into the peer's parity mbarrier (tx = 1024 B).
// smem floats: mbar[4] @0, hbuf [2][128][4] @4, xbuf [2][5][4] @1028,
//              gbuf [2 par][4 seg][256 row][5] @1068 -> 11308 floats
// ---------------------------------------------------------------------------
#define SMEM0_BYTES (11308 * 4)

__global__ void __cluster_dims__(2, 1, 1) __launch_bounds__(512, 1)
lstm_layer0(const float* __restrict__ x, const float* __restrict__ Wih,
            const float* __restrict__ Whh, const float* __restrict__ bih,
            const float* __restrict__ bhh)
{
    extern __shared__ float sm[];
    const uint32_t smb = smem_u32(sm);
    float* hbuf = sm + 4;      // [2 par][128 j][4 b]
    float* xbuf = sm + 1028;   // [2 par][5 d][4 b]
    float* gbuf = sm + 1068;   // [2 par][4 seg][256 row][5]

    const int tid  = threadIdx.x;
    const int rank = blockIdx.x & 1;
    const int b0   = (blockIdx.x >> 1) * 4;

    const int seg = tid >> 7;                 // 0..3 (constant within a warp)
    const int rp  = tid & 127;
    const int r0  = rp, r1 = rp + 128;        // two gate rows per thread
    const int kslice = (seg < 2) ? rank : (rank ^ 1);
    const int jbase  = kslice * 64 + (seg & 1) * 32;
    const int gr0 = ((r0 >> 6) << 7) + (rank << 6) + (r0 & 63);
    const int gr1 = ((r1 >> 6) << 7) + (rank << 6) + (r1 & 63);

    float4 wa[8], wb[8];                      // 32 j per row, 2 rows
    {
        const float4* s0 = (const float4*)(Whh + gr0 * 128 + jbase);
        const float4* s1 = (const float4*)(Whh + gr1 * 128 + jbase);
        #pragma unroll
        for (int kk = 0; kk < 8; ++kk) { wa[kk] = s0[kk]; wb[kk] = s1[kk]; }
    }
    unsigned long long wx0[5], wx1[5], bb0 = 0ull, bb1 = 0ull;
    if (seg == 0) {
        bb0 = pk2(bih[gr0] + bhh[gr0]);
        bb1 = pk2(bih[gr1] + bhh[gr1]);
        #pragma unroll
        for (int d = 0; d < 5; ++d) {
            wx0[d] = pk2(Wih[gr0 * 5 + d]);
            wx1[d] = pk2(Wih[gr1 * 5 + d]);
        }
    }

    if (tid == 0) {
        mbar_init(smb + 0, 1);
        mbar_init(smb + 8, 1);
        mbar_arm_tx(smb + 0, 1024);
        mbar_arm_tx(smb + 8, 1024);
    }
    for (int i = tid; i < 1024; i += 512) hbuf[i] = 0.f;
    if (tid < 20) {
        int b = tid / 5, d = tid % 5;
        xbuf[d * 4 + b] = x[((size_t)(b0 + b) * Tn) * 5 + d];
    }

    const int cb = tid & 3, cj = (tid >> 2) & 63;   // combine map (tid<256)
    const uint32_t peer = mapa_sh(smb, rank ^ 1);

    __syncthreads();
    cluster_sync_();   // mbarriers armed + hbuf zeroed cluster-wide
    if (tid == 0) {    // initial h(-1)=0 exchange: ship zeroed own slice
        fence_async_();
        uint32_t off = (4 + rank * 256) * 4;
        bulk_dsmem(peer + off, smb + off, 1024, peer + 0);
    }

    float c = 0.f;

    for (int t = 0; t < Tn; ++t) {
        const int par = t & 1, nb = par ^ 1;
        float pre = 0.f;
        if (tid < 20 && t + 1 < Tn) {
            int b = tid / 5, d = tid % 5;
            pre = x[((size_t)(b0 + b) * Tn + (t + 1)) * 5 + d];
        }
        unsigned long long a0lo = bb0, a0hi = bb0, a1lo = bb1, a1hi = bb1;
        if (seg == 0) {
            const float* xb = xbuf + par * 20;
            #pragma unroll
            for (int d = 0; d < 5; ++d) {
                unsigned long long xlo = *(const unsigned long long*)(xb + d * 4);
                unsigned long long xhi = *(const unsigned long long*)(xb + d * 4 + 2);
                ffma2(a0lo, wx0[d], xlo); ffma2(a0hi, wx0[d], xhi);
                ffma2(a1lo, wx1[d], xlo); ffma2(a1hi, wx1[d], xhi);
            }
        }
        const float* hp = hbuf + par * 512 + jbase * 4;
        if (seg < 2) {     // own slice: ready via bar2 of previous step
            #pragma unroll
            for (int kk = 0; kk < 8; ++kk) {
                float4 w0v = wa[kk], w1v = wb[kk];
                #pragma unroll
                for (int s = 0; s < 4; ++s) {
                    ulonglong2 hv = *(const ulonglong2*)(hp + (kk * 4 + s) * 4);
                    unsigned long long p0 = pk2(sel4(w0v, s));
                    ffma2(a0lo, p0, hv.x); ffma2(a0hi, p0, hv.y);
                    unsigned long long p1 = pk2(sel4(w1v, s));
                    ffma2(a1lo, p1, hv.x); ffma2(a1hi, p1, hv.y);
                }
            }
        }
        {   // wait for the peer slice of h(t-1); re-arm for t+2
            uint32_t mb = smb + par * 8;
            mbar_wait_cl(mb, (t >> 1) & 1);
            if (tid == 0) mbar_arm_tx(mb, 1024);
        }
        if (seg >= 2) {    // peer slice (delivered by bulk copies)
            #pragma unroll
            for (int kk = 0; kk < 8; ++kk) {
                float4 w0v = wa[kk], w1v = wb[kk];
                #pragma unroll
                for (int s = 0; s < 4; ++s) {
                    ulonglong2 hv = *(const ulonglong2*)(hp + (kk * 4 + s) * 4);
                    unsigned long long p0 = pk2(sel4(w0v, s));
                    ffma2(a0lo, p0, hv.x); ffma2(a0hi, p0, hv.y);
                    unsigned long long p1 = pk2(sel4(w1v, s));
                    ffma2(a1lo, p1, hv.x); ffma2(a1hi, p1, hv.y);
                }
            }
        }
        {   // gate partials, pitch 5: lane stride 5 (odd) -> conflict-free
            float* gp = gbuf + par * 5120 + seg * 1280;
            float v0, v1;
            unpk(a0lo, v0, v1); gp[r0 * 5 + 0] = v0; gp[r0 * 5 + 1] = v1;
            unpk(a0hi, v0, v1); gp[r0 * 5 + 2] = v0; gp[r0 * 5 + 3] = v1;
            unpk(a1lo, v0, v1); gp[r1 * 5 + 0] = v0; gp[r1 * 5 + 1] = v1;
            unpk(a1hi, v0, v1); gp[r1 * 5 + 2] = v0; gp[r1 * 5 + 3] = v1;
        }
        if (tid < 20 && t + 1 < Tn) {
            int b = tid / 5, d = tid % 5;
            xbuf[nb * 20 + d * 4 + b] = pre;
        }
        __syncthreads();                       // bar1: gbuf ready
        if (tid < 256) {
            const float* gq = gbuf + par * 5120;
            float gv[4];
            #pragma unroll
            for (int g = 0; g < 4; ++g) {
                int r = g * 64 + cj;
                gv[g] = gq[r * 5 + cb] + gq[1280 + r * 5 + cb]
                      + gq[2560 + r * 5 + cb] + gq[3840 + r * 5 + cb];
            }
            float ii = sigm(gv[0]), ff = sigm(gv[1]), g = tanh_(gv[2]), oo = sigm(gv[3]);
            c = fmaf(ff, c, ii * g);
            float h = oo * tanh_(c);
            hbuf[nb * 512 + rank * 256 + tid] = h;   // self slice, contiguous STS
            g_h1[((size_t)t * 128 + (rank << 6) + cj) * 256 + b0 + cb] = h;
            __syncwarp();
            if ((tid & 31) == 0) {                   // 1 bulk copy per warp region
                fence_async_();
                uint32_t off = (4 + nb * 512 + rank * 256 + (tid & 224)) * 4;
                bulk_dsmem(peer + off, smb + off, 128, peer + nb * 8);
            }
        }
        __syncthreads();                       // bar2: self h for next pre-wait
    }
    // consume the final exchange (exit safety without any cluster barrier)
    mbar_wait_cl(smb + 0, (Tn >> 1) & 1);
}

// ---------------------------------------------------------------------------
// Layer 1 + FC: cluster of 4 CTAs x 512 threads, 8 batches/cluster. Thread =
// (row-pair rp 0..63 -> rows rp & rp+64, K-segment seg 0..7 of 32 j): segs
// 0..3 = W_ih over h1_t (pre-wait), segs 4..7 = W_hh over h2_{t-1} (post-
// wait). Each h load feeds TWO rows. Exchange: combine writes h into a
// parity-doubled stage; each combine warp ships its 128B region to all 4
// ranks via bulk copies -> tx = 4 x 1024 B = 4096 B.
// smem floats: mbar[4] @0, hbuf [2][128][8] @4, sbuf [2][128][8] @2052,
//              stage [2][256] @4100, gbuf [2][8][128][9] @4612 -> 23044 floats
// ---------------------------------------------------------------------------
#define SMEM1_BYTES (23044 * 4)

__global__ void __cluster_dims__(4, 1, 1) __launch_bounds__(512, 1)
lstm_layer1(const float* __restrict__ Wih, const float* __restrict__ Whh,
            const float* __restrict__ bih, const float* __restrict__ bhh,
            const float* __restrict__ fcW, const float* __restrict__ fcb,
            float* __restrict__ out)
{
    extern __shared__ float sm[];
    const uint32_t smb = smem_u32(sm);
    float* hbuf  = sm + 4;     // [2 par][128 j][8 b]
    float* sbuf  = sm + 2052;  // [2 par][128 j][8 b]
    float* stage = sm + 4100;  // [2 par][256] outgoing h slice
    float* gbuf  = sm + 4612;  // [2 par][8 seg][128 row][9]

    const int tid  = threadIdx.x;
    const int rank = blockIdx.x & 3;
    const int b0   = (blockIdx.x >> 2) * 8;

    const int seg = tid >> 6;                 // 0..7 (constant within a warp)
    const int rp  = tid & 63;
    const int r0  = rp, r1 = rp + 64;         // two gate rows per thread
    const int gr0 = ((r0 >> 5) << 7) + (rank << 5) + (r0 & 31);
    const int gr1 = ((r1 >> 5) << 7) + (rank << 5) + (r1 & 31);

    float4 wa[8], wb[8];
    {
        const float* wmat = (seg < 4) ? Wih : Whh;
        const float4* s0 = (const float4*)(wmat + gr0 * 128 + (seg & 3) * 32);
        const float4* s1 = (const float4*)(wmat + gr1 * 128 + (seg & 3) * 32);
        #pragma unroll
        for (int kk = 0; kk < 8; ++kk) { wa[kk] = s0[kk]; wb[kk] = s1[kk]; }
    }
    unsigned long long bb0 = 0ull, bb1 = 0ull;
    if (seg == 0) {
        bb0 = pk2(bih[gr0] + bhh[gr0]);
        bb1 = pk2(bih[gr1] + bhh[gr1]);
    }

    if (tid == 0) {
        mbar_init(smb + 0, 1);
        mbar_init(smb + 8, 1);
        mbar_arm_tx(smb + 0, 4096);
        mbar_arm_tx(smb + 8, 4096);
    }
    for (int i = tid; i < 2048; i += 512) hbuf[i]  = 0.f;
    for (int i = tid; i < 512;  i += 512) stage[i] = 0.f;

    // h1 staging map (float2 per thread fully covers sbuf buffer 0)
    const int sj = tid >> 2, pq = tid & 3;
    {
        float2 v = *(const float2*)(g_h1 + (size_t)sj * 256 + b0 + pq * 2);
        *(float2*)(sbuf + sj * 8 + pq * 2) = v;
    }
    const int cb = tid & 7, cj = (tid >> 3) & 31;   // combine map (tid<256)
    uint32_t base[4];
    #pragma unroll
    for (int r = 0; r < 4; ++r) base[r] = mapa_sh(smb, r);

    __syncthreads();
    cluster_sync_();   // mbarriers armed + buffers zeroed cluster-wide
    if (tid < 4) {     // initial h2(-1)=0 exchange: ship zeroed stage0 slice
        fence_async_();
        bulk_dsmem(base[tid] + (4 + rank * 256) * 4, smb + 4100 * 4,
                   1024, base[tid] + 0);
    }

    float c = 0.f;
    unsigned long long a0[4], a1[4];

    for (int t = 0; t < Tn; ++t) {
        const int par = t & 1, nb = par ^ 1;
        float2 pre = make_float2(0.f, 0.f);
        if (t + 1 < Tn)
            pre = *(const float2*)(g_h1 + ((size_t)(t + 1) * 128 + sj) * 256 + b0 + pq * 2);

        #pragma unroll
        for (int i = 0; i < 4; ++i) { a0[i] = bb0; a1[i] = bb1; }

        const float* src = ((seg < 4) ? sbuf : hbuf) + par * 1024 + (seg & 3) * 256;
        if (seg < 4) {     // W_ih part: no cross-CTA dependency
            #pragma unroll
            for (int kk = 0; kk < 8; ++kk) {
                float4 w0v = wa[kk], w1v = wb[kk];
                #pragma unroll
                for (int s = 0; s < 4; ++s) {
                    const float* p = src + (kk * 4 + s) * 8;
                    ulonglong2 h0 = *(const ulonglong2*)(p);
                    ulonglong2 h1 = *(const ulonglong2*)(p + 4);
                    unsigned long long p0 = pk2(sel4(w0v, s));
                    ffma2(a0[0], p0, h0.x); ffma2(a0[1], p0, h0.y);
                    ffma2(a0[2], p0, h1.x); ffma2(a0[3], p0, h1.y);
                    unsigned long long p1 = pk2(sel4(w1v, s));
                    ffma2(a1[0], p1, h0.x); ffma2(a1[1], p1, h0.y);
                    ffma2(a1[2], p1, h1.x); ffma2(a1[3], p1, h1.y);
                }
            }
        }
        {   // wait for the full h2(t-1); re-arm for t+2
            uint32_t mb = smb + par * 8;
            mbar_wait_cl(mb, (t >> 1) & 1);
            if (tid == 0) mbar_arm_tx(mb, 4096);
        }
        if (seg >= 4) {    // W_hh part: after the h2 exchange
            #pragma unroll
            for (int kk = 0; kk < 8; ++kk) {
                float4 w0v = wa[kk], w1v = wb[kk];
                #pragma unroll
                for (int s = 0; s < 4; ++s) {
                    const float* p = src + (kk * 4 + s) * 8;
                    ulonglong2 h0 = *(const ulonglong2*)(p);
                    ulonglong2 h1 = *(const ulonglong2*)(p + 4);
                    unsigned long long p0 = pk2(sel4(w0v, s));
                    ffma2(a0[0], p0, h0.x); ffma2(a0[1], p0, h0.y);
                    ffma2(a0[2], p0, h1.x); ffma2(a0[3], p0, h1.y);
                    unsigned long long p1 = pk2(sel4(w1v, s));
                    ffma2(a1[0], p1, h0.x); ffma2(a1[1], p1, h0.y);
                    ffma2(a1[2], p1, h1.x); ffma2(a1[3], p1, h1.y);
                }
            }
        }
        {   // gate partials, pitch 9: lane stride 9 (odd) -> conflict-free
            float* gp = gbuf + (par * 8 + seg) * 1152;
            float v0, v1;
            #pragma unroll
            for (int i = 0; i < 4; ++i) {
                unpk(a0[i], v0, v1);
                gp[r0 * 9 + i * 2] = v0; gp[r0 * 9 + i * 2 + 1] = v1;
            }
            #pragma unroll
            for (int i = 0; i < 4; ++i) {
                unpk(a1[i], v0, v1);
                gp[r1 * 9 + i * 2] = v0; gp[r1 * 9 + i * 2 + 1] = v1;
            }
        }
        if (t + 1 < Tn) *(float2*)(sbuf + nb * 1024 + sj * 8 + pq * 2) = pre;
        __syncthreads();   // bar1: gbuf + sbuf[nb] ready

        if (tid < 256) {
            const float* gq = gbuf + par * 9216;
            float gv[4];
            #pragma unroll
            for (int g = 0; g < 4; ++g) {
                int r = g * 32 + cj;
                float s = 0.f;
                #pragma unroll
                for (int sg = 0; sg < 8; ++sg) s += gq[sg * 1152 + r * 9 + cb];
                gv[g] = s;
            }
            float ii = sigm(gv[0]), ff = sigm(gv[1]), g = tanh_(gv[2]), oo = sigm(gv[3]);
            c = fmaf(ff, c, ii * g);
            float h = oo * tanh_(c);
            stage[nb * 256 + tid] = h;          // contiguous per-warp regions
            __syncwarp();
            if ((tid & 31) < 4) {               // 4 copies per warp: one per rank
                int dr = tid & 31;
                fence_async_();
                uint32_t dsto = (4 + nb * 1024 + rank * 256 + (tid & 224)) * 4;
                uint32_t srco = (4100 + nb * 256 + (tid & 224)) * 4;
                bulk_dsmem(base[dr] + dsto, smb + srco, 128, base[dr] + nb * 8);
            }
        }
    }
    // consume the final exchange (buffer 0, T even) — also exit safety
    mbar_wait_cl(smb + 0, (Tn >> 1) & 1);

    // FC head: full final h2 in hbuf buffer 0 ([j][8] batch-major, async-delivered)
    if (rank == 0 && tid < 16) {
        int b = tid >> 1, cl = tid & 1;
        float s = fcb[cl];
        #pragma unroll
        for (int j = 0; j < 128; ++j) s = fmaf(hbuf[j * 8 + b], fcW[cl * 128 + j], s);
        out[(b0 + b) * 2 + cl] = s;
    }
}

// ---------------------------------------------------------------------------
extern "C" void kernel_launch(void* const* d_in, const int* in_sizes, int n_in,
                              void* d_out, int out_size)
{
    const float* x    = (const float*)d_in[0];
    const float* Wih0 = (const float*)d_in[1];
    const float* Whh0 = (const float*)d_in[2];
    const float* bih0 = (const float*)d_in[3];
    const float* bhh0 = (const float*)d_in[4];
    const float* Wih1 = (const float*)d_in[5];
    const float* Whh1 = (const float*)d_in[6];
    const float* bih1 = (const float*)d_in[7];
    const float* bhh1 = (const float*)d_in[8];
    const float* fcW  = (const float*)d_in[9];
    const float* fcb  = (const float*)d_in[10];
    float* out = (float*)d_out;

    cudaFuncSetAttribute(lstm_layer0, cudaFuncAttributeMaxDynamicSharedMemorySize, SMEM0_BYTES);
    cudaFuncSetAttribute(lstm_layer1, cudaFuncAttributeMaxDynamicSharedMemorySize, SMEM1_BYTES);

    lstm_layer0<<<128, 512, SMEM0_BYTES>>>(x, Wih0, Whh0, bih0, bhh0);
    lstm_layer1<<<128, 512, SMEM1_BYTES>>>(Wih1, Whh1, bih1, bhh1, fcW, fcb, out);
}